// round 9
// baseline (speedup 1.0000x reference)
#include <cuda_runtime.h>
#include <cuda_fp16.h>
#include <math.h>

#define EDIM 128
#define NH 8
#define NB 2
#define TS 4096
#define HEDIM 1024   // NH*EDIM
#define BT 8192      // NB*TS

// Scratch (device globals; no runtime allocation)
__device__ __half g_Qh[(size_t)BT * HEDIM];
__device__ __half g_Kh[(size_t)BT * HEDIM];
__device__ __half g_Vh[(size_t)BT * HEDIM];
__device__ float  g_Op[(size_t)BT * HEDIM];

// ---------------------------------------------------------------------------
// fp32 GEMM, fp16 epilogue with scale: C = h16(scale * A@B).
// ---------------------------------------------------------------------------
__global__ __launch_bounds__(256) void gemm_h16s(const float* __restrict__ A,
                                                 const float* __restrict__ B,
                                                 __half* __restrict__ C,
                                                 int M, int N, int K,
                                                 float scale) {
    __shared__ float sA[64][33];
    __shared__ float sB[32][64];
    const int tid = threadIdx.x;
    const int tx = tid & 15, ty = tid >> 4;
    const int n0 = blockIdx.x << 6, m0 = blockIdx.y << 6;
    float acc[4][4] = {};
    for (int k0 = 0; k0 < K; k0 += 32) {
#pragma unroll
        for (int i = 0; i < 8; ++i) {
            int idx = tid + (i << 8);
            int r = idx >> 5, c = idx & 31;
            sA[r][c] = A[(size_t)(m0 + r) * K + (k0 + c)];
        }
#pragma unroll
        for (int i = 0; i < 8; ++i) {
            int idx = tid + (i << 8);
            int r = idx >> 6, c = idx & 63;
            sB[r][c] = B[(size_t)(k0 + r) * N + (n0 + c)];
        }
        __syncthreads();
#pragma unroll
        for (int kk = 0; kk < 32; ++kk) {
            float a0 = sA[(ty << 2) + 0][kk];
            float a1 = sA[(ty << 2) + 1][kk];
            float a2 = sA[(ty << 2) + 2][kk];
            float a3 = sA[(ty << 2) + 3][kk];
            float4 b4 = *(const float4*)&sB[kk][tx << 2];
            acc[0][0] += a0 * b4.x; acc[0][1] += a0 * b4.y;
            acc[0][2] += a0 * b4.z; acc[0][3] += a0 * b4.w;
            acc[1][0] += a1 * b4.x; acc[1][1] += a1 * b4.y;
            acc[1][2] += a1 * b4.z; acc[1][3] += a1 * b4.w;
            acc[2][0] += a2 * b4.x; acc[2][1] += a2 * b4.y;
            acc[2][2] += a2 * b4.z; acc[2][3] += a2 * b4.w;
            acc[3][0] += a3 * b4.x; acc[3][1] += a3 * b4.y;
            acc[3][2] += a3 * b4.z; acc[3][3] += a3 * b4.w;
        }
        __syncthreads();
    }
#pragma unroll
    for (int i = 0; i < 4; ++i) {
        size_t base = (size_t)(m0 + (ty << 2) + i) * N + n0 + (tx << 2);
        *(__half2*)&C[base] =
            __floats2half2_rn(acc[i][0] * scale, acc[i][1] * scale);
        *(__half2*)&C[base + 2] =
            __floats2half2_rn(acc[i][2] * scale, acc[i][3] * scale);
    }
}

// fp32 GEMM (final output projection).
__global__ __launch_bounds__(256) void gemm_k(const float* __restrict__ A,
                                              const float* __restrict__ B,
                                              float* __restrict__ C,
                                              int M, int N, int K) {
    __shared__ float sA[64][33];
    __shared__ float sB[32][64];
    const int tid = threadIdx.x;
    const int tx = tid & 15, ty = tid >> 4;
    const int n0 = blockIdx.x << 6, m0 = blockIdx.y << 6;
    float acc[4][4] = {};
    for (int k0 = 0; k0 < K; k0 += 32) {
#pragma unroll
        for (int i = 0; i < 8; ++i) {
            int idx = tid + (i << 8);
            int r = idx >> 5, c = idx & 31;
            sA[r][c] = A[(size_t)(m0 + r) * K + (k0 + c)];
        }
#pragma unroll
        for (int i = 0; i < 8; ++i) {
            int idx = tid + (i << 8);
            int r = idx >> 6, c = idx & 63;
            sB[r][c] = B[(size_t)(k0 + r) * N + (n0 + c)];
        }
        __syncthreads();
#pragma unroll
        for (int kk = 0; kk < 32; ++kk) {
            float a0 = sA[(ty << 2) + 0][kk];
            float a1 = sA[(ty << 2) + 1][kk];
            float a2 = sA[(ty << 2) + 2][kk];
            float a3 = sA[(ty << 2) + 3][kk];
            float4 b4 = *(const float4*)&sB[kk][tx << 2];
            acc[0][0] += a0 * b4.x; acc[0][1] += a0 * b4.y;
            acc[0][2] += a0 * b4.z; acc[0][3] += a0 * b4.w;
            acc[1][0] += a1 * b4.x; acc[1][1] += a1 * b4.y;
            acc[1][2] += a1 * b4.z; acc[1][3] += a1 * b4.w;
            acc[2][0] += a2 * b4.x; acc[2][1] += a2 * b4.y;
            acc[2][2] += a2 * b4.z; acc[2][3] += a2 * b4.w;
            acc[3][0] += a3 * b4.x; acc[3][1] += a3 * b4.y;
            acc[3][2] += a3 * b4.z; acc[3][3] += a3 * b4.w;
        }
        __syncthreads();
    }
#pragma unroll
    for (int i = 0; i < 4; ++i)
#pragma unroll
        for (int j = 0; j < 4; ++j)
            C[(size_t)(m0 + (ty << 2) + i) * N + n0 + (tx << 2) + j] = acc[i][j];
}

// ---------------------------------------------------------------------------
// Flash attention (FA2 layout): 4 warps, each owns 16 full rows.
// Register-P, warp-local softmax. K double-buffered, V single-buffered
// (V(n+1) issued post-PV sync, lands during S(n+1)). 3 CTAs/SM target.
// ---------------------------------------------------------------------------
#define BM 64
#define BN 64
#define NT (TS / BN)
#define STRH 136            // halves per row (272B; 272%128==16 -> ldsm ok)
#define STRB 272

#define HOFF_Q  0
#define HOFF_K0 (HOFF_Q  + BM * STRH)   // 8704
#define HOFF_K1 (HOFF_K0 + BN * STRH)   // 17408
#define HOFF_V  (HOFF_K1 + BN * STRH)   // 26112
#define HOFF_END (HOFF_V + BN * STRH)   // 34816
#define SM_BYTES (HOFF_END * 2)         // 69632

#define LDSM4(r0, r1, r2, r3, p)                                              \
    asm volatile("ldmatrix.sync.aligned.m8n8.x4.shared.b16 {%0,%1,%2,%3},[%4];" \
                 : "=r"(r0), "=r"(r1), "=r"(r2), "=r"(r3) : "r"(p))
#define LDSM4T(r0, r1, r2, r3, p)                                             \
    asm volatile("ldmatrix.sync.aligned.m8n8.x4.trans.shared.b16 {%0,%1,%2,%3},[%4];" \
                 : "=r"(r0), "=r"(r1), "=r"(r2), "=r"(r3) : "r"(p))

#define MMA16816(d, a0, a1, a2, a3, b0, b1)                                   \
    asm volatile(                                                             \
        "mma.sync.aligned.m16n8k16.row.col.f32.f16.f16.f32 "                  \
        "{%0,%1,%2,%3},{%4,%5,%6,%7},{%8,%9},{%0,%1,%2,%3};"                  \
        : "+f"(d[0]), "+f"(d[1]), "+f"(d[2]), "+f"(d[3])                      \
        : "r"(a0), "r"(a1), "r"(a2), "r"(a3), "r"(b0), "r"(b1))

#define CPA16(dst, src)                                                       \
    asm volatile("cp.async.cg.shared.global [%0], [%1], 16;" ::               \
                 "r"(dst), "l"(src))
#define CP_COMMIT() asm volatile("cp.async.commit_group;")
#define CP_WAIT1()  asm volatile("cp.async.wait_group 1;")
#define CP_WAIT0()  asm volatile("cp.async.wait_group 0;")

__device__ __forceinline__ float ex2f(float x) {
    float r;
    asm("ex2.approx.ftz.f32 %0, %1;" : "=f"(r) : "f"(x));
    return r;
}
__device__ __forceinline__ unsigned packh2(float a, float b) {
    __half2 h = __floats2half2_rn(a, b);
    return *(unsigned*)&h;
}

__global__ __launch_bounds__(128, 3) void flash_attn_fa2(
    const __half* __restrict__ Qg, const __half* __restrict__ Kg,
    const __half* __restrict__ Vg, float* __restrict__ Og) {
    extern __shared__ __align__(16) char smem[];

    const int tid = threadIdx.x;
    const int wid = tid >> 5;       // 0..3, owns rows wid*16..wid*16+15
    const int lane = tid & 31;
    const int g = lane >> 2;        // row-in-8
    const int tg = lane & 3;        // thread-in-group

    const int h = blockIdx.y, b = blockIdx.z;
    const int q0 = blockIdx.x * BM;

    const size_t bh_off = (size_t)b * TS * HEDIM + (size_t)h * EDIM;
    const __half* Qbh = Qg + bh_off;
    const __half* Kbh = Kg + bh_off;
    const __half* Vbh = Vg + bh_off;
    float* Obh = Og + bh_off;

    const unsigned sbase = (unsigned)__cvta_generic_to_shared(smem);
    // A-frag gather (Q): rows wid*16 + (lane&15), 16B col-chunk (lane>>4)
    const unsigned aQ0 = sbase + HOFF_Q * 2 +
        (wid * 16 + (lane & 15)) * STRB + (lane >> 4) * 16;
    // B-frag gather (K, non-trans)
    const unsigned kpat =
        ((lane & 7) + ((lane >> 4) & 1) * 8) * STRB + ((lane >> 3) & 1) * 16;
    // B-frag gather (V, trans)
    const unsigned vpat =
        ((lane & 7) + ((lane >> 3) & 1) * 8) * STRB + (lane >> 4) * 16;
    const unsigned aK[2] = {sbase + HOFF_K0 * 2 + kpat,
                            sbase + HOFF_K1 * 2 + kpat};
    const unsigned aVb = sbase + HOFF_V * 2 + vpat;
    const unsigned dV = sbase + HOFF_V * 2;

    // ---- group 1: Q + K0; group 2: V0 ----
    {
        const unsigned dQ = sbase + HOFF_Q * 2;
        const unsigned dK = sbase + HOFF_K0 * 2;
#pragma unroll
        for (int i = 0; i < 8; ++i) {
            int idx = tid + (i << 7);          // 0..1023
            int r = idx >> 4, c = idx & 15;
            const size_t goff = (size_t)r * HEDIM + c * 8;
            const unsigned soff = r * STRB + c * 16;
            CPA16(dQ + soff, Qbh + (size_t)q0 * HEDIM + goff);
            CPA16(dK + soff, Kbh + goff);
        }
        CP_COMMIT();
#pragma unroll
        for (int i = 0; i < 8; ++i) {
            int idx = tid + (i << 7);
            int r = idx >> 4, c = idx & 15;
            CPA16(dV + r * STRB + c * 16, Vbh + (size_t)r * HEDIM + c * 8);
        }
        CP_COMMIT();
    }

    const int row0 = wid * 16 + g;
    const int row1 = row0 + 8;

    float m0 = -INFINITY, m1 = -INFINITY, l0s = 0.f, l1s = 0.f;
    float o[16][4];
#pragma unroll
    for (int nb = 0; nb < 16; ++nb)
#pragma unroll
        for (int j = 0; j < 4; ++j) o[nb][j] = 0.f;

    for (int n = 0; n < NT; ++n) {
        const int buf = n & 1;
        // ---- prefetch K(n+1) into the other K buffer ----
        if (n + 1 < NT) {
            const unsigned dK = sbase + (buf ? HOFF_K0 : HOFF_K1) * 2;
            const size_t kvg = (size_t)(n + 1) * BN * HEDIM;
#pragma unroll
            for (int i = 0; i < 8; ++i) {
                int idx = tid + (i << 7);
                int r = idx >> 4, c = idx & 15;
                CPA16(dK + r * STRB + c * 16, Kbh + kvg + (size_t)r * HEDIM + c * 8);
            }
            CP_COMMIT();
            CP_WAIT1();   // everything except K(n+1) done: K(n), V(n) ready
        } else {
            CP_WAIT0();
        }
        __syncthreads();

        // ---- S = Q @ K^T over full 64 cols (Q frags reloaded per ks) ----
        float s[8][4];
#pragma unroll
        for (int nb = 0; nb < 8; ++nb)
#pragma unroll
            for (int j = 0; j < 4; ++j) s[nb][j] = 0.f;

        unsigned ak = aK[buf];
#pragma unroll
        for (int ks = 0; ks < 8; ++ks) {
            unsigned q0r, q1r, q2r, q3r;
            LDSM4(q0r, q1r, q2r, q3r, aQ0 + ks * 32);
#pragma unroll
            for (int nb2 = 0; nb2 < 4; ++nb2) {
                unsigned b0, b1, b2, b3;
                LDSM4(b0, b1, b2, b3, ak + nb2 * 16 * STRB);
                MMA16816(s[nb2 * 2 + 0], q0r, q1r, q2r, q3r, b0, b1);
                MMA16816(s[nb2 * 2 + 1], q0r, q1r, q2r, q3r, b2, b3);
            }
            ak += 32;
        }

        // ---- warp-local online softmax (base-2; scale folded upstream) ----
        float mx0 = -INFINITY, mx1 = -INFINITY;
#pragma unroll
        for (int nb = 0; nb < 8; ++nb) {
            mx0 = fmaxf(mx0, fmaxf(s[nb][0], s[nb][1]));
            mx1 = fmaxf(mx1, fmaxf(s[nb][2], s[nb][3]));
        }
        mx0 = fmaxf(mx0, __shfl_xor_sync(0xffffffffu, mx0, 1));
        mx0 = fmaxf(mx0, __shfl_xor_sync(0xffffffffu, mx0, 2));
        mx1 = fmaxf(mx1, __shfl_xor_sync(0xffffffffu, mx1, 1));
        mx1 = fmaxf(mx1, __shfl_xor_sync(0xffffffffu, mx1, 2));
        const float mn0 = fmaxf(m0, mx0), mn1 = fmaxf(m1, mx1);
        const float al0 = ex2f(m0 - mn0), al1 = ex2f(m1 - mn1);
        m0 = mn0; m1 = mn1;

        float ps0 = 0.f, ps1 = 0.f;
        unsigned ph[8][2];
#pragma unroll
        for (int nb = 0; nb < 8; ++nb) {
            s[nb][0] = ex2f(s[nb][0] - mn0);
            s[nb][1] = ex2f(s[nb][1] - mn0);
            s[nb][2] = ex2f(s[nb][2] - mn1);
            s[nb][3] = ex2f(s[nb][3] - mn1);
            ps0 += s[nb][0] + s[nb][1];
            ps1 += s[nb][2] + s[nb][3];
            ph[nb][0] = packh2(s[nb][0], s[nb][1]);   // row g
            ph[nb][1] = packh2(s[nb][2], s[nb][3]);   // row g+8
        }
        ps0 += __shfl_xor_sync(0xffffffffu, ps0, 1);
        ps0 += __shfl_xor_sync(0xffffffffu, ps0, 2);
        ps1 += __shfl_xor_sync(0xffffffffu, ps1, 1);
        ps1 += __shfl_xor_sync(0xffffffffu, ps1, 2);
        l0s = l0s * al0 + ps0;
        l1s = l1s * al1 + ps1;

        // rescale O
#pragma unroll
        for (int nb = 0; nb < 16; ++nb) {
            o[nb][0] *= al0; o[nb][1] *= al0;
            o[nb][2] *= al1; o[nb][3] *= al1;
        }

        // ---- O += P @ V (P from registers; full 128 cols) ----
        unsigned av0 = aVb;
#pragma unroll
        for (int ks = 0; ks < 4; ++ks) {
            const unsigned pa0 = ph[2 * ks][0], pa1 = ph[2 * ks][1];
            const unsigned pa2 = ph[2 * ks + 1][0], pa3 = ph[2 * ks + 1][1];
            unsigned av = av0;
#pragma unroll
            for (int np = 0; np < 8; ++np) {
                unsigned v0, v1, v2, v3;
                LDSM4T(v0, v1, v2, v3, av);
                MMA16816(o[np * 2 + 0], pa0, pa1, pa2, pa3, v0, v1);
                MMA16816(o[np * 2 + 1], pa0, pa1, pa2, pa3, v2, v3);
                av += 32;
            }
            av0 += 16 * STRB;
        }
        __syncthreads();  // all warps done with V(n) + K(n) before overwrite

        // ---- now safe: prefetch V(n+1) into the (single) V buffer ----
        if (n + 1 < NT) {
            const size_t kvg = (size_t)(n + 1) * BN * HEDIM;
#pragma unroll
            for (int i = 0; i < 8; ++i) {
                int idx = tid + (i << 7);
                int r = idx >> 4, c = idx & 15;
                CPA16(dV + r * STRB + c * 16, Vbh + kvg + (size_t)r * HEDIM + c * 8);
            }
            CP_COMMIT();
        }
    }

    // ---- normalize + write O ----
    const float inv0 = 1.f / l0s, inv1 = 1.f / l1s;
#pragma unroll
    for (int nb = 0; nb < 16; ++nb) {
        const int col = nb * 8 + 2 * tg;
        float2 r0v = make_float2(o[nb][0] * inv0, o[nb][1] * inv0);
        float2 r1v = make_float2(o[nb][2] * inv1, o[nb][3] * inv1);
        *(float2*)&Obh[(size_t)(q0 + row0) * HEDIM + col] = r0v;
        *(float2*)&Obh[(size_t)(q0 + row1) * HEDIM + col] = r1v;
    }
}

// ---------------------------------------------------------------------------
extern "C" void kernel_launch(void* const* d_in, const int* in_sizes, int n_in,
                              void* d_out, int out_size) {
    (void)in_sizes; (void)n_in; (void)out_size;
    const float* k  = (const float*)d_in[0];
    const float* q  = (const float*)d_in[1];
    const float* v  = (const float*)d_in[2];
    const float* Wk = (const float*)d_in[3];
    const float* Wq = (const float*)d_in[4];
    const float* Wv = (const float*)d_in[5];
    const float* Wu = (const float*)d_in[6];
    float* out = (float*)d_out;

    __half *gQ, *gK, *gV;
    float* gO;
    cudaGetSymbolAddress((void**)&gQ, g_Qh);
    cudaGetSymbolAddress((void**)&gK, g_Kh);
    cudaGetSymbolAddress((void**)&gV, g_Vh);
    cudaGetSymbolAddress((void**)&gO, g_Op);

    cudaFuncSetAttribute(flash_attn_fa2,
                         cudaFuncAttributeMaxDynamicSharedMemorySize, SM_BYTES);

    // log2(e)/sqrt(128) folded into Q projection (softmax runs in base 2)
    const float qscale = 0.12751744f;
    dim3 blk(256);
    dim3 gproj(HEDIM / 64, BT / 64);
    gemm_h16s<<<gproj, blk>>>(q, Wq, gQ, BT, HEDIM, EDIM, qscale);
    gemm_h16s<<<gproj, blk>>>(k, Wk, gK, BT, HEDIM, EDIM, 1.0f);
    gemm_h16s<<<gproj, blk>>>(v, Wv, gV, BT, HEDIM, EDIM, 1.0f);

    dim3 gatt(TS / BM, NH, NB);
    flash_attn_fa2<<<gatt, dim3(128), SM_BYTES>>>(gQ, gK, gV, gO);

    dim3 gout(EDIM / 64, BT / 64);
    gemm_k<<<gout, blk>>>(gO, Wu, out, BT, EDIM, HEDIM);
}